// round 7
// baseline (speedup 1.0000x reference)
#include <cuda_runtime.h>
#include <cuda_bf16.h>

#define NN   50000
#define NBLK 782          // ceil(50000/64)
#define HSZ  132          // activation smem stride (floats) — conflict-free for LDS.32
#define WST  40           // weight k-slice stride (floats)  — conflict-free for LDS.64
#define WFT  136          // full-weight smem stride (floats)

// ---------------- device scratch (statics; no runtime allocs) ----------------
__device__ float g_P  [(size_t)NN * 512];   // projected inputs + bias, per layer
__device__ float g_H  [(size_t)NN * 128];   // layer-1 output (post-ReLU)
__device__ float g_Hn [(size_t)NN * 128];   // LSTM final hidden per node
__device__ float g_Wih[512 * 128];          // tf32-rounded, k-permuted weights
__device__ float g_Whh[512 * 128];
__device__ float g_Wself [128 * 128];
__device__ float g_Wneigh[128 * 128];
__device__ float g_bsum[512];
__device__ float g_bout[128];

// ---------------- helpers ----------------
__device__ __forceinline__ unsigned tf32u(float f) {
    unsigned u; asm("cvt.rna.tf32.f32 %0, %1;" : "=r"(u) : "f"(f)); return u;
}
__device__ __forceinline__ float tf32f(float f) { return __uint_as_float(tf32u(f)); }

__device__ __forceinline__ float sigf(float x)  { return __fdividef(1.f, 1.f + __expf(-x)); }
__device__ __forceinline__ float tanh_(float x) { return 2.f * sigf(2.f * x) - 1.f; }

__device__ __forceinline__ void mma8(float* c, unsigned a0, unsigned a1, unsigned a2,
                                     unsigned a3, unsigned b0, unsigned b1) {
    asm volatile("mma.sync.aligned.m16n8k8.row.col.f32.tf32.tf32.f32 "
                 "{%0,%1,%2,%3}, {%4,%5,%6,%7}, {%8,%9}, {%0,%1,%2,%3};"
                 : "+f"(c[0]), "+f"(c[1]), "+f"(c[2]), "+f"(c[3])
                 : "r"(a0), "r"(a1), "r"(a2), "r"(a3), "r"(b0), "r"(b1));
}
__device__ __forceinline__ void cpa16(float* dst, const float* src) {
    unsigned d = (unsigned)__cvta_generic_to_shared(dst);
    asm volatile("cp.async.cg.shared.global [%0], [%1], 16;" :: "r"(d), "l"(src));
}
__device__ __forceinline__ void cpcommit() { asm volatile("cp.async.commit_group;"); }

// stage permuted W[:, ks*32 : ks*32+32] (512x128 row-major) into buf[n*WST + c]
__device__ __forceinline__ void stage512(float* buf, const float* __restrict__ W,
                                         int ks, int tid) {
#pragma unroll
    for (int i = 0; i < 8; i++) {
        int idx = tid + i * 512;
        int n = idx >> 3, c = idx & 7;
        cpa16(buf + n * WST + c * 4, W + n * 128 + ks * 32 + c * 4);
    }
    cpcommit();
}

// acc[4 gates][4 tiles][4 frags] += As[64x128] @ W^T   (W: 512x128, tf32, k-permuted)
__device__ __forceinline__ void gemm512(float (&acc)[4][4][4], const float* As,
                                        float* d0, float* d1, const float* __restrict__ W,
                                        int rowA, int rowB, int gid, int tig, int cg, int tid) {
    stage512(d0, W, 0, tid);
#pragma unroll
    for (int ks = 0; ks < 4; ks++) {
        const float* cur = (ks & 1) ? d1 : d0;
        if (ks < 3) {
            stage512((ks & 1) ? d0 : d1, W, ks + 1, tid);
            asm volatile("cp.async.wait_group 1;");
        } else {
            asm volatile("cp.async.wait_group 0;");
        }
        __syncthreads();
#pragma unroll
        for (int kc = 0; kc < 4; kc++) {
            int kk = ks * 32 + kc * 8;
            unsigned a0 = tf32u(As[rowA * HSZ + kk + tig]);
            unsigned a1 = tf32u(As[rowB * HSZ + kk + tig]);
            unsigned a2 = tf32u(As[rowA * HSZ + kk + tig + 4]);
            unsigned a3 = tf32u(As[rowB * HSZ + kk + tig + 4]);
#pragma unroll
            for (int g = 0; g < 4; g++)
#pragma unroll
                for (int tt = 0; tt < 4; tt++) {
                    float2 b = *(const float2*)&cur[(g * 128 + cg * 32 + tt * 8 + gid) * WST
                                                    + kc * 8 + 2 * tig];
                    mma8(acc[g][tt], a0, a1, a2, a3,
                         __float_as_uint(b.x), __float_as_uint(b.y));
                }
        }
        __syncthreads();
    }
}

// ---------------- prep: tf32-round + k-permute weights, fold biases ----------------
__global__ void prep_kernel(const float* __restrict__ wih, const float* __restrict__ whh,
                            const float* __restrict__ bih, const float* __restrict__ bhh,
                            const float* __restrict__ wself, const float* __restrict__ wneigh,
                            const float* __restrict__ bo, int hout) {
    int i = blockIdx.x * 256 + threadIdx.x;
    if (i < 512 * 128) {
        int n = i >> 7, k = i & 127;
        int kp = (k & ~7) | ((k & 3) << 1) | ((k >> 2) & 1);  // pair (k, k+4) adjacent
        g_Wih[n * 128 + kp] = tf32f(wih[i]);
        g_Whh[n * 128 + kp] = tf32f(whh[i]);
    }
    if (i < hout * 128) {
        int n = i >> 7, k = i & 127;
        int kp = (k & ~7) | ((k & 3) << 1) | ((k >> 2) & 1);
        g_Wself[n * 128 + kp]  = tf32f(wself[i]);
        g_Wneigh[n * 128 + kp] = tf32f(wneigh[i]);
    }
    if (i < 512)  g_bsum[i] = bih[i] + bhh[i];
    if (i < 128 && i < hout) g_bout[i] = bo[i];
}

// ---------------- proj: P = x @ Wih^T + bsum ----------------
__global__ void __launch_bounds__(512, 1) proj_kernel(const float* __restrict__ xext, int sel) {
    extern __shared__ float sm[];
    float* xs = sm;
    float* d0 = sm + 64 * HSZ;
    float* d1 = d0 + 512 * WST;
    const float* x = sel ? g_H : xext;
    int tid = threadIdx.x, lane = tid & 31, warp = tid >> 5;
    int wr = warp >> 2, cg = warp & 3, gid = lane >> 2, tig = lane & 3;
    int base = blockIdx.x * 64;
    int rowA = wr * 16 + gid, rowB = rowA + 8;
    bool vA = base + rowA < NN, vB = base + rowB < NN;

#pragma unroll
    for (int i = 0; i < 4; i++) {
        int idx = tid + i * 512;
        int r = idx >> 5, c = idx & 31;
        if (base + r < NN) cpa16(xs + r * HSZ + c * 4, x + (size_t)(base + r) * 128 + c * 4);
    }
    cpcommit();

    float acc[4][4][4];
#pragma unroll
    for (int g = 0; g < 4; g++)
#pragma unroll
        for (int tt = 0; tt < 4; tt++)
#pragma unroll
            for (int s = 0; s < 4; s++) acc[g][tt][s] = 0.f;

    gemm512(acc, xs, d0, d1, g_Wih, rowA, rowB, gid, tig, cg, tid);

    size_t nA = (size_t)(base + rowA) * 512, nB = (size_t)(base + rowB) * 512;
#pragma unroll
    for (int g = 0; g < 4; g++)
#pragma unroll
        for (int tt = 0; tt < 4; tt++) {
            int col = g * 128 + cg * 32 + tt * 8 + 2 * tig;
            float2 bb = *(const float2*)&g_bsum[col];
            if (vA) { float2 v = make_float2(acc[g][tt][0] + bb.x, acc[g][tt][1] + bb.y);
                      *(float2*)&g_P[nA + col] = v; }
            if (vB) { float2 v = make_float2(acc[g][tt][2] + bb.x, acc[g][tt][3] + bb.y);
                      *(float2*)&g_P[nB + col] = v; }
        }
}

// ---------------- lstm: 16-step recurrent aggregation ----------------
__global__ void __launch_bounds__(512, 1) lstm_kernel(const int* __restrict__ nbr) {
    extern __shared__ float sm[];
    float* hs = sm;
    float* d0 = sm + 64 * HSZ;
    float* d1 = d0 + 512 * WST;
    int*  snbr = (int*)(d1 + 512 * WST);
    int tid = threadIdx.x, lane = tid & 31, warp = tid >> 5;
    int wr = warp >> 2, cg = warp & 3, gid = lane >> 2, tig = lane & 3;
    int base = blockIdx.x * 64;
    int rowA = wr * 16 + gid, rowB = rowA + 8;
    bool vA = base + rowA < NN, vB = base + rowB < NN;

    for (int i = tid; i < 64 * HSZ; i += 512) hs[i] = 0.f;
#pragma unroll
    for (int i = 0; i < 2; i++) {
        int idx = tid + i * 512;
        int r = idx >> 4;
        snbr[idx] = (base + r < NN) ? nbr[(size_t)(base + r) * 16 + (idx & 15)] : 0;
    }
    __syncthreads();

    float cst[4][4];
#pragma unroll
    for (int tt = 0; tt < 4; tt++)
#pragma unroll
        for (int s = 0; s < 4; s++) cst[tt][s] = 0.f;

    for (int t = 0; t < 16; t++) {
        float acc[4][4][4];
        const float* PA = g_P + (size_t)snbr[rowA * 16 + t] * 512;
        const float* PB = g_P + (size_t)snbr[rowB * 16 + t] * 512;
#pragma unroll
        for (int g = 0; g < 4; g++)
#pragma unroll
            for (int tt = 0; tt < 4; tt++) {
                int col = g * 128 + cg * 32 + tt * 8 + 2 * tig;
                float2 va = vA ? *(const float2*)&PA[col] : make_float2(0.f, 0.f);
                float2 vb = vB ? *(const float2*)&PB[col] : make_float2(0.f, 0.f);
                acc[g][tt][0] = va.x; acc[g][tt][1] = va.y;
                acc[g][tt][2] = vb.x; acc[g][tt][3] = vb.y;
            }

        gemm512(acc, hs, d0, d1, g_Whh, rowA, rowB, gid, tig, cg, tid);

#pragma unroll
        for (int tt = 0; tt < 4; tt++)
#pragma unroll
            for (int s = 0; s < 4; s++) {
                float iv = sigf(acc[0][tt][s]);
                float fv = sigf(acc[1][tt][s]);
                float gv = tanh_(acc[2][tt][s]);
                float ov = sigf(acc[3][tt][s]);
                float c = fv * cst[tt][s] + iv * gv;
                cst[tt][s] = c;
                int row = (s < 2) ? rowA : rowB;
                int u = cg * 32 + tt * 8 + 2 * tig + (s & 1);
                hs[row * HSZ + u] = ov * tanh_(c);
            }
        // gemm512's internal first __syncthreads orders these writes before next-step reads
    }
    __syncthreads();
    for (int i = tid; i < 64 * 128; i += 512) {
        int r = i >> 7, u = i & 127;
        if (base + r < NN) g_Hn[(size_t)(base + r) * 128 + u] = hs[r * HSZ + u];
    }
}

// ---------------- out: o = x@Wself^T + hN@Wneigh^T + b  (+ ReLU / sigmoid) ----------------
template<int HOUT, int ACT>
__global__ void __launch_bounds__(512, 1) out_kernel(const float* __restrict__ xext, int sel,
                                                     float* __restrict__ oext, int osel) {
    extern __shared__ float sm[];
    float* xs = sm;
    float* h2 = xs + 64 * HSZ;
    float* ws = h2 + 64 * HSZ;
    float* wn = ws + HOUT * WFT;
    const float* x = sel ? g_H : xext;
    float* o = osel ? oext : g_H;
    int tid = threadIdx.x, lane = tid & 31, warp = tid >> 5;
    int wr = warp >> 2, cg = warp & 3, gid = lane >> 2, tig = lane & 3;
    int base = blockIdx.x * 64;
    int rowA = wr * 16 + gid, rowB = rowA + 8;
    bool vA = base + rowA < NN, vB = base + rowB < NN;

#pragma unroll
    for (int i = 0; i < 4; i++) {
        int idx = tid + i * 512;
        int r = idx >> 5, c = idx & 31;
        if (base + r < NN) {
            cpa16(xs + r * HSZ + c * 4, x   + (size_t)(base + r) * 128 + c * 4);
            cpa16(h2 + r * HSZ + c * 4, g_Hn + (size_t)(base + r) * 128 + c * 4);
        }
    }
#pragma unroll
    for (int i = 0; i < HOUT * 32 / 512; i++) {
        int idx = tid + i * 512;
        int n = idx >> 5, c = idx & 31;
        cpa16(ws + n * WFT + c * 4, g_Wself  + n * 128 + c * 4);
        cpa16(wn + n * WFT + c * 4, g_Wneigh + n * 128 + c * 4);
    }
    cpcommit();
    asm volatile("cp.async.wait_group 0;");
    __syncthreads();

    constexpr int T = HOUT / 32;
    float acc[T][4];
#pragma unroll
    for (int tt = 0; tt < T; tt++)
#pragma unroll
        for (int s = 0; s < 4; s++) acc[tt][s] = 0.f;

#pragma unroll
    for (int p = 0; p < 2; p++) {
        const float* As = p ? h2 : xs;
        const float* W  = p ? wn : ws;
#pragma unroll
        for (int kc = 0; kc < 16; kc++) {
            int kk = kc * 8;
            unsigned a0 = tf32u(As[rowA * HSZ + kk + tig]);
            unsigned a1 = tf32u(As[rowB * HSZ + kk + tig]);
            unsigned a2 = tf32u(As[rowA * HSZ + kk + tig + 4]);
            unsigned a3 = tf32u(As[rowB * HSZ + kk + tig + 4]);
#pragma unroll
            for (int tt = 0; tt < T; tt++) {
                float2 b = *(const float2*)&W[(cg * (HOUT / 4) + tt * 8 + gid) * WFT
                                              + kk + 2 * tig];
                mma8(acc[tt], a0, a1, a2, a3, __float_as_uint(b.x), __float_as_uint(b.y));
            }
        }
    }
#pragma unroll
    for (int tt = 0; tt < T; tt++)
#pragma unroll
        for (int s = 0; s < 4; s++) {
            int u = cg * (HOUT / 4) + tt * 8 + 2 * tig + (s & 1);
            float v = acc[tt][s] + g_bout[u];
            v = ACT ? sigf(v) : fmaxf(v, 0.f);
            int row = (s < 2) ? rowA : rowB;
            bool vv = (s < 2) ? vA : vB;
            if (vv) o[(size_t)(base + row) * HOUT + u] = v;
        }
}

// ---------------- launch ----------------
extern "C" void kernel_launch(void* const* d_in, const int* in_sizes, int n_in,
                              void* d_out, int out_size) {
    const float* feats = (const float*)d_in[0];
    const int*   nbr   = (const int*)d_in[1];

    const int PSM  = (64 * HSZ + 2 * 512 * WST) * 4;             // 197632
    const int LSM  = PSM + 64 * 16 * 4;                          // 201728
    const int OSM1 = (2 * 64 * HSZ + 2 * 128 * WFT) * 4;         // 206848
    const int OSM2 = (2 * 64 * HSZ + 2 * 64 * WFT) * 4;          // 137216
    cudaFuncSetAttribute(proj_kernel,       cudaFuncAttributeMaxDynamicSharedMemorySize, PSM);
    cudaFuncSetAttribute(lstm_kernel,       cudaFuncAttributeMaxDynamicSharedMemorySize, LSM);
    cudaFuncSetAttribute(out_kernel<128,0>, cudaFuncAttributeMaxDynamicSharedMemorySize, OSM1);
    cudaFuncSetAttribute(out_kernel<64,1>,  cudaFuncAttributeMaxDynamicSharedMemorySize, OSM2);

    dim3 g(NBLK), b(512);

    // layer 1
    prep_kernel<<<256, 256>>>((const float*)d_in[2], (const float*)d_in[3],
                              (const float*)d_in[4], (const float*)d_in[5],
                              (const float*)d_in[6], (const float*)d_in[7],
                              (const float*)d_in[8], 128);
    proj_kernel<<<g, b, PSM>>>(feats, 0);
    lstm_kernel<<<g, b, LSM>>>(nbr);
    out_kernel<128, 0><<<g, b, OSM1>>>(feats, 0, nullptr, 0);

    // layer 2
    prep_kernel<<<256, 256>>>((const float*)d_in[9],  (const float*)d_in[10],
                              (const float*)d_in[11], (const float*)d_in[12],
                              (const float*)d_in[13], (const float*)d_in[14],
                              (const float*)d_in[15], 64);
    proj_kernel<<<g, b, PSM>>>(nullptr, 1);
    lstm_kernel<<<g, b, LSM>>>(nbr);
    out_kernel<64, 1><<<g, b, OSM2>>>(nullptr, 1, (float*)d_out, 1);
}

// round 8
// speedup vs baseline: 1.6128x; 1.6128x over previous
#include <cuda_runtime.h>
#include <cuda_bf16.h>

#define NN   50000
#define NBLK 782          // ceil(50000/64)
#define HSZ  132          // fp32 activation smem stride (proj/out kernels)
#define WST  40           // fp32 weight k-slice stride (proj kernel)
#define WFT  136          // fp32 full-weight smem stride (out kernel)
#define BST  144          // bf16 smem stride (lstm): 288B = 72 words == 8 mod 32 -> conflict-free

// ---------------- device scratch (statics; no runtime allocs) ----------------
__device__ float g_P  [(size_t)NN * 512];   // projected inputs + bias, per layer
__device__ float g_H  [(size_t)NN * 128];   // layer-1 output (post-ReLU)
__device__ float g_Hn [(size_t)NN * 128];   // LSTM final hidden per node
__device__ float g_Wih[512 * 128];          // tf32, k8-permuted (proj)
__device__ __nv_bfloat16 g_WhhB[512 * 128]; // bf16, k16-permuted (lstm)
__device__ float g_Wself [128 * 128];       // tf32, k8-permuted (out)
__device__ float g_Wneigh[128 * 128];
__device__ float g_bsum[512];
__device__ float g_bout[128];

// ---------------- helpers ----------------
__device__ __forceinline__ unsigned tf32u(float f) {
    unsigned u; asm("cvt.rna.tf32.f32 %0, %1;" : "=r"(u) : "f"(f)); return u;
}
__device__ __forceinline__ float tf32f(float f) { return __uint_as_float(tf32u(f)); }

__device__ __forceinline__ float sigf(float x)  { return __fdividef(1.f, 1.f + __expf(-x)); }
__device__ __forceinline__ float tanh_(float x) { return 2.f * sigf(2.f * x) - 1.f; }

__device__ __forceinline__ void mma8(float* c, unsigned a0, unsigned a1, unsigned a2,
                                     unsigned a3, unsigned b0, unsigned b1) {
    asm volatile("mma.sync.aligned.m16n8k8.row.col.f32.tf32.tf32.f32 "
                 "{%0,%1,%2,%3}, {%4,%5,%6,%7}, {%8,%9}, {%0,%1,%2,%3};"
                 : "+f"(c[0]), "+f"(c[1]), "+f"(c[2]), "+f"(c[3])
                 : "r"(a0), "r"(a1), "r"(a2), "r"(a3), "r"(b0), "r"(b1));
}
__device__ __forceinline__ void mma16(float* c, unsigned a0, unsigned a1, unsigned a2,
                                      unsigned a3, unsigned b0, unsigned b1) {
    asm volatile("mma.sync.aligned.m16n8k16.row.col.f32.bf16.bf16.f32 "
                 "{%0,%1,%2,%3}, {%4,%5,%6,%7}, {%8,%9}, {%0,%1,%2,%3};"
                 : "+f"(c[0]), "+f"(c[1]), "+f"(c[2]), "+f"(c[3])
                 : "r"(a0), "r"(a1), "r"(a2), "r"(a3), "r"(b0), "r"(b1));
}
__device__ __forceinline__ unsigned packbf2(float hi, float lo) {
    unsigned r; asm("cvt.rn.bf16x2.f32 %0, %1, %2;" : "=r"(r) : "f"(hi), "f"(lo)); return r;
}
__device__ __forceinline__ void cpa16(void* dst, const void* src) {
    unsigned d = (unsigned)__cvta_generic_to_shared(dst);
    asm volatile("cp.async.cg.shared.global [%0], [%1], 16;" :: "r"(d), "l"(src));
}
__device__ __forceinline__ void cpcommit() { asm volatile("cp.async.commit_group;"); }

// k16 permutation: within each 16-block put logical pairs {2t,2t+1},{2t+8,2t+9} adjacent
__device__ __forceinline__ int perm16(int k) {
    return (k & ~15) | ((k & 6) << 1) | ((k & 8) >> 2) | (k & 1);
}

// ---- tf32 helpers for proj (unchanged from R7) ----
__device__ __forceinline__ void stage512(float* buf, const float* __restrict__ W,
                                         int ks, int tid) {
#pragma unroll
    for (int i = 0; i < 8; i++) {
        int idx = tid + i * 512;
        int n = idx >> 3, c = idx & 7;
        cpa16(buf + n * WST + c * 4, W + n * 128 + ks * 32 + c * 4);
    }
    cpcommit();
}
__device__ __forceinline__ void gemm512(float (&acc)[4][4][4], const float* As,
                                        float* d0, float* d1, const float* __restrict__ W,
                                        int rowA, int rowB, int gid, int tig, int cg, int tid) {
    stage512(d0, W, 0, tid);
#pragma unroll
    for (int ks = 0; ks < 4; ks++) {
        const float* cur = (ks & 1) ? d1 : d0;
        if (ks < 3) {
            stage512((ks & 1) ? d0 : d1, W, ks + 1, tid);
            asm volatile("cp.async.wait_group 1;");
        } else {
            asm volatile("cp.async.wait_group 0;");
        }
        __syncthreads();
#pragma unroll
        for (int kc = 0; kc < 4; kc++) {
            int kk = ks * 32 + kc * 8;
            unsigned a0 = tf32u(As[rowA * HSZ + kk + tig]);
            unsigned a1 = tf32u(As[rowB * HSZ + kk + tig]);
            unsigned a2 = tf32u(As[rowA * HSZ + kk + tig + 4]);
            unsigned a3 = tf32u(As[rowB * HSZ + kk + tig + 4]);
#pragma unroll
            for (int g = 0; g < 4; g++)
#pragma unroll
                for (int tt = 0; tt < 4; tt++) {
                    float2 b = *(const float2*)&cur[(g * 128 + cg * 32 + tt * 8 + gid) * WST
                                                    + kc * 8 + 2 * tig];
                    mma8(acc[g][tt], a0, a1, a2, a3,
                         __float_as_uint(b.x), __float_as_uint(b.y));
                }
        }
        __syncthreads();
    }
}

// ---------------- prep ----------------
__global__ void prep_kernel(const float* __restrict__ wih, const float* __restrict__ whh,
                            const float* __restrict__ bih, const float* __restrict__ bhh,
                            const float* __restrict__ wself, const float* __restrict__ wneigh,
                            const float* __restrict__ bo, int hout) {
    int i = blockIdx.x * 256 + threadIdx.x;
    if (i < 512 * 128) {
        int n = i >> 7, k = i & 127;
        int kp = (k & ~7) | ((k & 3) << 1) | ((k >> 2) & 1);  // tf32 k8 perm
        g_Wih[n * 128 + kp] = tf32f(wih[i]);
        g_WhhB[n * 128 + perm16(k)] = __float2bfloat16(whh[i]);
    }
    if (i < hout * 128) {
        int n = i >> 7, k = i & 127;
        int kp = (k & ~7) | ((k & 3) << 1) | ((k >> 2) & 1);
        g_Wself[n * 128 + kp]  = tf32f(wself[i]);
        g_Wneigh[n * 128 + kp] = tf32f(wneigh[i]);
    }
    if (i < 512)  g_bsum[i] = bih[i] + bhh[i];
    if (i < 128 && i < hout) g_bout[i] = bo[i];
}

// ---------------- proj: P = x @ Wih^T + bsum (tf32) ----------------
__global__ void __launch_bounds__(512, 1) proj_kernel(const float* __restrict__ xext, int sel) {
    extern __shared__ float sm[];
    float* xs = sm;
    float* d0 = sm + 64 * HSZ;
    float* d1 = d0 + 512 * WST;
    const float* x = sel ? g_H : xext;
    int tid = threadIdx.x, lane = tid & 31, warp = tid >> 5;
    int wr = warp >> 2, cg = warp & 3, gid = lane >> 2, tig = lane & 3;
    int base = blockIdx.x * 64;
    int rowA = wr * 16 + gid, rowB = rowA + 8;
    bool vA = base + rowA < NN, vB = base + rowB < NN;

#pragma unroll
    for (int i = 0; i < 4; i++) {
        int idx = tid + i * 512;
        int r = idx >> 5, c = idx & 31;
        if (base + r < NN) cpa16(xs + r * HSZ + c * 4, x + (size_t)(base + r) * 128 + c * 4);
    }
    cpcommit();

    float acc[4][4][4];
#pragma unroll
    for (int g = 0; g < 4; g++)
#pragma unroll
        for (int tt = 0; tt < 4; tt++)
#pragma unroll
            for (int s = 0; s < 4; s++) acc[g][tt][s] = 0.f;

    gemm512(acc, xs, d0, d1, g_Wih, rowA, rowB, gid, tig, cg, tid);

    size_t nA = (size_t)(base + rowA) * 512, nB = (size_t)(base + rowB) * 512;
#pragma unroll
    for (int g = 0; g < 4; g++)
#pragma unroll
        for (int tt = 0; tt < 4; tt++) {
            int col = g * 128 + cg * 32 + tt * 8 + 2 * tig;
            float2 bb = *(const float2*)&g_bsum[col];
            if (vA) { float2 v = make_float2(acc[g][tt][0] + bb.x, acc[g][tt][1] + bb.y);
                      *(float2*)&g_P[nA + col] = v; }
            if (vB) { float2 v = make_float2(acc[g][tt][2] + bb.x, acc[g][tt][3] + bb.y);
                      *(float2*)&g_P[nB + col] = v; }
        }
}

// ---------------- lstm: bf16 recurrence, W_hh smem-resident, h double-buffered --------
__global__ void __launch_bounds__(512, 1) lstm_kernel(const int* __restrict__ nbr) {
    extern __shared__ char smraw[];
    __nv_bfloat16* wsm  = (__nv_bfloat16*)smraw;          // 512 x BST
    __nv_bfloat16* hbuf = wsm + 512 * BST;                // 2 x 64 x BST
    int* snbr = (int*)(hbuf + 2 * 64 * BST);              // 64 x 16

    int tid = threadIdx.x, lane = tid & 31, warp = tid >> 5;
    int wr = warp >> 2, cg = warp & 3, gid = lane >> 2, tig = lane & 3;
    int base = blockIdx.x * 64;
    int rowA = wr * 16 + gid, rowB = rowA + 8;

    // stage W_hh (bf16, k16-permuted) once: 512 rows x 256B into 288B-stride slots
#pragma unroll
    for (int i = 0; i < 16; i++) {
        int idx = tid + i * 512;
        int n = idx >> 4, c = idx & 15;
        cpa16(wsm + n * BST + c * 8, g_WhhB + n * 128 + c * 8);
    }
    cpcommit();
    // zero h buffer 0
    for (int i = tid; i < 64 * BST / 2; i += 512) ((unsigned*)hbuf)[i] = 0;
    // stage neighbor lists
#pragma unroll
    for (int i = 0; i < 2; i++) {
        int idx = tid + i * 512;
        int r = idx >> 4;
        snbr[idx] = (base + r < NN) ? nbr[(size_t)(base + r) * 16 + (idx & 15)] : 0;
    }
    asm volatile("cp.async.wait_group 0;");
    __syncthreads();

    float cst[4][4];
#pragma unroll
    for (int tt = 0; tt < 4; tt++)
#pragma unroll
        for (int s = 0; s < 4; s++) cst[tt][s] = 0.f;

    const char* wbase = (const char*)wsm;
    int colbase = cg * 32 + 2 * tig;

    for (int t = 0; t < 16; t++) {
        const char* hc = (const char*)(hbuf + (t & 1) * 64 * BST);
        char*       hn = (char*)(hbuf + ((t + 1) & 1) * 64 * BST);

        // gate init from gathered P rows (fp32, L2-resident)
        float acc[4][4][4];
        {
            const float* PA = g_P + (size_t)snbr[rowA * 16 + t] * 512;
            const float* PB = g_P + (size_t)snbr[rowB * 16 + t] * 512;
#pragma unroll
            for (int g = 0; g < 4; g++)
#pragma unroll
                for (int tt = 0; tt < 4; tt++) {
                    int col = g * 128 + colbase + tt * 8;
                    float2 va = *(const float2*)&PA[col];
                    float2 vb = *(const float2*)&PB[col];
                    acc[g][tt][0] = va.x; acc[g][tt][1] = va.y;
                    acc[g][tt][2] = vb.x; acc[g][tt][3] = vb.y;
                }
        }

        // acc += h @ Whh^T   (bf16 m16n8k16, 8 k-chunks)
#pragma unroll
        for (int kc = 0; kc < 8; kc++) {
            uint2 va = *(const uint2*)(hc + rowA * (BST * 2) + kc * 32 + tig * 8);
            uint2 vb = *(const uint2*)(hc + rowB * (BST * 2) + kc * 32 + tig * 8);
#pragma unroll
            for (int g = 0; g < 4; g++)
#pragma unroll
                for (int tt = 0; tt < 4; tt++) {
                    int n = g * 128 + cg * 32 + tt * 8 + gid;
                    uint2 b = *(const uint2*)(wbase + n * (BST * 2) + kc * 32 + tig * 8);
                    mma16(acc[g][tt], va.x, vb.x, va.y, vb.y, b.x, b.y);
                }
        }

        // cell update (registers) + write h_next (bf16x2 stores, conflict-free)
#pragma unroll
        for (int tt = 0; tt < 4; tt++) {
            int u = colbase + tt * 8;                       // even
            int phys = (u & ~15) | ((u & 6) << 1) | ((u & 8) >> 2);
            float hv[4];
#pragma unroll
            for (int s = 0; s < 4; s++) {
                float iv = sigf(acc[0][tt][s]);
                float fv = sigf(acc[1][tt][s]);
                float gv = tanh_(acc[2][tt][s]);
                float ov = sigf(acc[3][tt][s]);
                float c = fv * cst[tt][s] + iv * gv;
                cst[tt][s] = c;
                hv[s] = ov * tanh_(c);
            }
            *(unsigned*)(hn + rowA * (BST * 2) + phys * 2) = packbf2(hv[1], hv[0]);
            *(unsigned*)(hn + rowB * (BST * 2) + phys * 2) = packbf2(hv[3], hv[2]);
        }
        __syncthreads();   // writes of h_next visible before next step's reads
    }

    // final hidden lives in buffer 0 (t=15 wrote buf[(16)&1]=0); un-permute to g_Hn fp32
    const __nv_bfloat16* hf = hbuf;
    for (int i = tid; i < 64 * 128; i += 512) {
        int r = i >> 7, u = i & 127;
        if (base + r < NN)
            g_Hn[(size_t)(base + r) * 128 + u] = __bfloat162float(hf[r * BST + perm16(u)]);
    }
}

// ---------------- out: o = x@Wself^T + hN@Wneigh^T + b  (+ ReLU / sigmoid) ----------------
template<int HOUT, int ACT>
__global__ void __launch_bounds__(512, 1) out_kernel(const float* __restrict__ xext, int sel,
                                                     float* __restrict__ oext, int osel) {
    extern __shared__ float sm[];
    float* xs = sm;
    float* h2 = xs + 64 * HSZ;
    float* ws = h2 + 64 * HSZ;
    float* wn = ws + HOUT * WFT;
    const float* x = sel ? g_H : xext;
    float* o = osel ? oext : g_H;
    int tid = threadIdx.x, lane = tid & 31, warp = tid >> 5;
    int wr = warp >> 2, cg = warp & 3, gid = lane >> 2, tig = lane & 3;
    int base = blockIdx.x * 64;
    int rowA = wr * 16 + gid, rowB = rowA + 8;
    bool vA = base + rowA < NN, vB = base + rowB < NN;

#pragma unroll
    for (int i = 0; i < 4; i++) {
        int idx = tid + i * 512;
        int r = idx >> 5, c = idx & 31;
        if (base + r < NN) {
            cpa16(xs + r * HSZ + c * 4, x    + (size_t)(base + r) * 128 + c * 4);
            cpa16(h2 + r * HSZ + c * 4, g_Hn + (size_t)(base + r) * 128 + c * 4);
        }
    }
#pragma unroll
    for (int i = 0; i < HOUT * 32 / 512; i++) {
        int idx = tid + i * 512;
        int n = idx >> 5, c = idx & 31;
        cpa16(ws + n * WFT + c * 4, g_Wself  + n * 128 + c * 4);
        cpa16(wn + n * WFT + c * 4, g_Wneigh + n * 128 + c * 4);
    }
    cpcommit();
    asm volatile("cp.async.wait_group 0;");
    __syncthreads();

    constexpr int T = HOUT / 32;
    float acc[T][4];
#pragma unroll
    for (int tt = 0; tt < T; tt++)
#pragma unroll
        for (int s = 0; s < 4; s++) acc[tt][s] = 0.f;

#pragma unroll
    for (int p = 0; p < 2; p++) {
        const float* As = p ? h2 : xs;
        const float* W  = p ? wn : ws;
#pragma unroll
        for (int kc = 0; kc < 16; kc++) {
            int kk = kc * 8;
            unsigned a0 = tf32u(As[rowA * HSZ + kk + tig]);
            unsigned a1 = tf32u(As[rowB * HSZ + kk + tig]);
            unsigned a2 = tf32u(As[rowA * HSZ + kk + tig + 4]);
            unsigned a3 = tf32u(As[rowB * HSZ + kk + tig + 4]);
#pragma unroll
            for (int tt = 0; tt < T; tt++) {
                float2 b = *(const float2*)&W[(cg * (HOUT / 4) + tt * 8 + gid) * WFT
                                              + kk + 2 * tig];
                mma8(acc[tt], a0, a1, a2, a3, __float_as_uint(b.x), __float_as_uint(b.y));
            }
        }
    }
#pragma unroll
    for (int tt = 0; tt < T; tt++)
#pragma unroll
        for (int s = 0; s < 4; s++) {
            int u = cg * (HOUT / 4) + tt * 8 + 2 * tig + (s & 1);
            float v = acc[tt][s] + g_bout[u];
            v = ACT ? sigf(v) : fmaxf(v, 0.f);
            int row = (s < 2) ? rowA : rowB;
            bool vv = (s < 2) ? vA : vB;
            if (vv) o[(size_t)(base + row) * HOUT + u] = v;
        }
}

// ---------------- launch ----------------
extern "C" void kernel_launch(void* const* d_in, const int* in_sizes, int n_in,
                              void* d_out, int out_size) {
    const float* feats = (const float*)d_in[0];
    const int*   nbr   = (const int*)d_in[1];

    const int PSM  = (64 * HSZ + 2 * 512 * WST) * 4;                 // 197632
    const int LSM  = 512 * BST * 2 + 2 * 64 * BST * 2 + 64 * 16 * 4; // 188416
    const int OSM1 = (2 * 64 * HSZ + 2 * 128 * WFT) * 4;             // 206848
    const int OSM2 = (2 * 64 * HSZ + 2 * 64 * WFT) * 4;              // 137216
    cudaFuncSetAttribute(proj_kernel,       cudaFuncAttributeMaxDynamicSharedMemorySize, PSM);
    cudaFuncSetAttribute(lstm_kernel,       cudaFuncAttributeMaxDynamicSharedMemorySize, LSM);
    cudaFuncSetAttribute(out_kernel<128,0>, cudaFuncAttributeMaxDynamicSharedMemorySize, OSM1);
    cudaFuncSetAttribute(out_kernel<64,1>,  cudaFuncAttributeMaxDynamicSharedMemorySize, OSM2);

    dim3 g(NBLK), b(512);

    // layer 1
    prep_kernel<<<256, 256>>>((const float*)d_in[2], (const float*)d_in[3],
                              (const float*)d_in[4], (const float*)d_in[5],
                              (const float*)d_in[6], (const float*)d_in[7],
                              (const float*)d_in[8], 128);
    proj_kernel<<<g, b, PSM>>>(feats, 0);
    lstm_kernel<<<g, b, LSM>>>(nbr);
    out_kernel<128, 0><<<g, b, OSM1>>>(feats, 0, nullptr, 0);

    // layer 2
    prep_kernel<<<256, 256>>>((const float*)d_in[9],  (const float*)d_in[10],
                              (const float*)d_in[11], (const float*)d_in[12],
                              (const float*)d_in[13], (const float*)d_in[14],
                              (const float*)d_in[15], 64);
    proj_kernel<<<g, b, PSM>>>(nullptr, 1);
    lstm_kernel<<<g, b, LSM>>>(nbr);
    out_kernel<64, 1><<<g, b, OSM2>>>(nullptr, 1, (float*)d_out, 1);
}

// round 9
// speedup vs baseline: 1.9228x; 1.1922x over previous
#include <cuda_runtime.h>
#include <cuda_bf16.h>

#define NN   50000
#define NBLK 782          // ceil(50000/64)
#define HSZ  132          // fp32 activation smem stride (proj/out kernels)
#define WST  40           // fp32 weight k-slice stride (proj kernel)
#define WFT  136          // fp32 full-weight smem stride (out kernel)
#define BST  144          // bf16 smem stride (lstm): 288B -> conflict-free LDS.64 per phase

// ---------------- device scratch (statics; no runtime allocs) ----------------
__device__ float g_P  [(size_t)NN * 512];   // projected inputs + bias, per layer
__device__ float g_H  [(size_t)NN * 128];   // layer-1 output (post-ReLU)
__device__ float g_Hn [(size_t)NN * 128];   // LSTM final hidden per node
__device__ float g_Wih[512 * 128];          // tf32, k8-permuted (proj)
__device__ __nv_bfloat16 g_WhhB[512 * 128]; // bf16, k16-permuted (lstm)
__device__ float g_Wself [128 * 128];       // tf32, k8-permuted (out)
__device__ float g_Wneigh[128 * 128];
__device__ float g_bsum[512];
__device__ float g_bout[128];

// ---------------- helpers ----------------
__device__ __forceinline__ unsigned tf32u(float f) {
    unsigned u; asm("cvt.rna.tf32.f32 %0, %1;" : "=r"(u) : "f"(f)); return u;
}
__device__ __forceinline__ float tf32f(float f) { return __uint_as_float(tf32u(f)); }

__device__ __forceinline__ float sigf(float x)  { return __fdividef(1.f, 1.f + __expf(-x)); }

__device__ __forceinline__ float tanha(float x) {
    float y; asm("tanh.approx.f32 %0, %1;" : "=f"(y) : "f"(x)); return y;
}
__device__ __forceinline__ float siga(float x) {
    return fmaf(0.5f, tanha(0.5f * x), 0.5f);
}

__device__ __forceinline__ void mma8(float* c, unsigned a0, unsigned a1, unsigned a2,
                                     unsigned a3, unsigned b0, unsigned b1) {
    asm volatile("mma.sync.aligned.m16n8k8.row.col.f32.tf32.tf32.f32 "
                 "{%0,%1,%2,%3}, {%4,%5,%6,%7}, {%8,%9}, {%0,%1,%2,%3};"
                 : "+f"(c[0]), "+f"(c[1]), "+f"(c[2]), "+f"(c[3])
                 : "r"(a0), "r"(a1), "r"(a2), "r"(a3), "r"(b0), "r"(b1));
}
__device__ __forceinline__ void mma16(float* c, unsigned a0, unsigned a1, unsigned a2,
                                      unsigned a3, unsigned b0, unsigned b1) {
    asm volatile("mma.sync.aligned.m16n8k16.row.col.f32.bf16.bf16.f32 "
                 "{%0,%1,%2,%3}, {%4,%5,%6,%7}, {%8,%9}, {%0,%1,%2,%3};"
                 : "+f"(c[0]), "+f"(c[1]), "+f"(c[2]), "+f"(c[3])
                 : "r"(a0), "r"(a1), "r"(a2), "r"(a3), "r"(b0), "r"(b1));
}
__device__ __forceinline__ unsigned packbf2(float hi, float lo) {
    unsigned r; asm("cvt.rn.bf16x2.f32 %0, %1, %2;" : "=r"(r) : "f"(hi), "f"(lo)); return r;
}
__device__ __forceinline__ void cpa16(void* dst, const void* src) {
    unsigned d = (unsigned)__cvta_generic_to_shared(dst);
    asm volatile("cp.async.cg.shared.global [%0], [%1], 16;" :: "r"(d), "l"(src));
}
__device__ __forceinline__ void cpcommit() { asm volatile("cp.async.commit_group;"); }

// k16 permutation: within each 16-block put logical pairs {2t,2t+1},{2t+8,2t+9} adjacent
__device__ __forceinline__ int perm16(int k) {
    return (k & ~15) | ((k & 6) << 1) | ((k & 8) >> 2) | (k & 1);
}

// ---- tf32 helpers for proj ----
__device__ __forceinline__ void stage512(float* buf, const float* __restrict__ W,
                                         int ks, int tid) {
#pragma unroll
    for (int i = 0; i < 8; i++) {
        int idx = tid + i * 512;
        int n = idx >> 3, c = idx & 7;
        cpa16(buf + n * WST + c * 4, W + n * 128 + ks * 32 + c * 4);
    }
    cpcommit();
}
__device__ __forceinline__ void gemm512(float (&acc)[4][4][4], const float* As,
                                        float* d0, float* d1, const float* __restrict__ W,
                                        int rowA, int rowB, int gid, int tig, int cg, int tid) {
    stage512(d0, W, 0, tid);
#pragma unroll
    for (int ks = 0; ks < 4; ks++) {
        const float* cur = (ks & 1) ? d1 : d0;
        if (ks < 3) {
            stage512((ks & 1) ? d0 : d1, W, ks + 1, tid);
            asm volatile("cp.async.wait_group 1;");
        } else {
            asm volatile("cp.async.wait_group 0;");
        }
        __syncthreads();
#pragma unroll
        for (int kc = 0; kc < 4; kc++) {
            int kk = ks * 32 + kc * 8;
            unsigned a0 = tf32u(As[rowA * HSZ + kk + tig]);
            unsigned a1 = tf32u(As[rowB * HSZ + kk + tig]);
            unsigned a2 = tf32u(As[rowA * HSZ + kk + tig + 4]);
            unsigned a3 = tf32u(As[rowB * HSZ + kk + tig + 4]);
#pragma unroll
            for (int g = 0; g < 4; g++)
#pragma unroll
                for (int tt = 0; tt < 4; tt++) {
                    float2 b = *(const float2*)&cur[(g * 128 + cg * 32 + tt * 8 + gid) * WST
                                                    + kc * 8 + 2 * tig];
                    mma8(acc[g][tt], a0, a1, a2, a3,
                         __float_as_uint(b.x), __float_as_uint(b.y));
                }
        }
        __syncthreads();
    }
}

// ---------------- prep ----------------
__global__ void prep_kernel(const float* __restrict__ wih, const float* __restrict__ whh,
                            const float* __restrict__ bih, const float* __restrict__ bhh,
                            const float* __restrict__ wself, const float* __restrict__ wneigh,
                            const float* __restrict__ bo, int hout) {
    int i = blockIdx.x * 256 + threadIdx.x;
    if (i < 512 * 128) {
        int n = i >> 7, k = i & 127;
        int kp = (k & ~7) | ((k & 3) << 1) | ((k >> 2) & 1);  // tf32 k8 perm
        g_Wih[n * 128 + kp] = tf32f(wih[i]);
        g_WhhB[n * 128 + perm16(k)] = __float2bfloat16(whh[i]);
    }
    if (i < hout * 128) {
        int n = i >> 7, k = i & 127;
        int kp = (k & ~7) | ((k & 3) << 1) | ((k >> 2) & 1);
        g_Wself[n * 128 + kp]  = tf32f(wself[i]);
        g_Wneigh[n * 128 + kp] = tf32f(wneigh[i]);
    }
    if (i < 512)  g_bsum[i] = bih[i] + bhh[i];
    if (i < 128 && i < hout) g_bout[i] = bo[i];
}

// ---------------- proj: P = x @ Wih^T + bsum (tf32) ----------------
__global__ void __launch_bounds__(512, 1) proj_kernel(const float* __restrict__ xext, int sel) {
    extern __shared__ float sm[];
    float* xs = sm;
    float* d0 = sm + 64 * HSZ;
    float* d1 = d0 + 512 * WST;
    const float* x = sel ? g_H : xext;
    int tid = threadIdx.x, lane = tid & 31, warp = tid >> 5;
    int wr = warp >> 2, cg = warp & 3, gid = lane >> 2, tig = lane & 3;
    int base = blockIdx.x * 64;
    int rowA = wr * 16 + gid, rowB = rowA + 8;
    bool vA = base + rowA < NN, vB = base + rowB < NN;

#pragma unroll
    for (int i = 0; i < 4; i++) {
        int idx = tid + i * 512;
        int r = idx >> 5, c = idx & 31;
        if (base + r < NN) cpa16(xs + r * HSZ + c * 4, x + (size_t)(base + r) * 128 + c * 4);
    }
    cpcommit();

    float acc[4][4][4];
#pragma unroll
    for (int g = 0; g < 4; g++)
#pragma unroll
        for (int tt = 0; tt < 4; tt++)
#pragma unroll
            for (int s = 0; s < 4; s++) acc[g][tt][s] = 0.f;

    gemm512(acc, xs, d0, d1, g_Wih, rowA, rowB, gid, tig, cg, tid);

    size_t nA = (size_t)(base + rowA) * 512, nB = (size_t)(base + rowB) * 512;
#pragma unroll
    for (int g = 0; g < 4; g++)
#pragma unroll
        for (int tt = 0; tt < 4; tt++) {
            int col = g * 128 + cg * 32 + tt * 8 + 2 * tig;
            float2 bb = *(const float2*)&g_bsum[col];
            if (vA) { float2 v = make_float2(acc[g][tt][0] + bb.x, acc[g][tt][1] + bb.y);
                      *(float2*)&g_P[nA + col] = v; }
            if (vB) { float2 v = make_float2(acc[g][tt][2] + bb.x, acc[g][tt][3] + bb.y);
                      *(float2*)&g_P[nB + col] = v; }
        }
}

// ---------------- lstm: Wn=16 warp layout, tanh.approx, gather-ahead ----------------
__global__ void __launch_bounds__(512, 1) lstm_kernel(const int* __restrict__ nbr) {
    extern __shared__ char smraw[];
    __nv_bfloat16* wsm  = (__nv_bfloat16*)smraw;          // 512 x BST
    __nv_bfloat16* hbuf = wsm + 512 * BST;                // 2 x 64 x BST
    int* snbr = (int*)(hbuf + 2 * 64 * BST);              // 64 x 16

    int tid = threadIdx.x, lane = tid & 31, warp = tid >> 5;
    int gid = lane >> 2, tig = lane & 3;
    int base = blockIdx.x * 64;

    // stage W_hh (bf16, k16-permuted) once
#pragma unroll
    for (int i = 0; i < 16; i++) {
        int idx = tid + i * 512;
        int n = idx >> 4, c = idx & 15;
        cpa16(wsm + n * BST + c * 8, g_WhhB + n * 128 + c * 8);
    }
    cpcommit();
    for (int i = tid; i < 64 * BST / 2; i += 512) ((unsigned*)hbuf)[i] = 0;  // zero h buf 0
#pragma unroll
    for (int i = 0; i < 2; i++) {
        int idx = tid + i * 512;
        int r = idx >> 4;
        snbr[idx] = (base + r < NN) ? nbr[(size_t)(base + r) * 16 + (idx & 15)] : 0;
    }
    asm volatile("cp.async.wait_group 0;");
    __syncthreads();

    const char* wbase = (const char*)wsm;
    int cb = warp * 8 + 2 * tig;                    // this warp's column pair base (per gate)
    int u = warp * 8 + 2 * tig;
    int phys = (u & ~15) | ((u & 6) << 1) | ((u & 8) >> 2);

    float cst[4][4];
#pragma unroll
    for (int m = 0; m < 4; m++)
#pragma unroll
        for (int s = 0; s < 4; s++) cst[m][s] = 0.f;

    float acc[4][4][4];   // [gate][m-tile][frag]
    // pre-gather step 0 gate init from P
#pragma unroll
    for (int m = 0; m < 4; m++) {
        const float* PA = g_P + (size_t)snbr[(m * 16 + gid) * 16 + 0] * 512;
        const float* PB = g_P + (size_t)snbr[(m * 16 + 8 + gid) * 16 + 0] * 512;
#pragma unroll
        for (int g = 0; g < 4; g++) {
            float2 va = *(const float2*)&PA[g * 128 + cb];
            float2 vb = *(const float2*)&PB[g * 128 + cb];
            acc[g][m][0] = va.x; acc[g][m][1] = va.y;
            acc[g][m][2] = vb.x; acc[g][m][3] = vb.y;
        }
    }

    for (int t = 0; t < 16; t++) {
        const char* hc = (const char*)(hbuf + (t & 1) * 64 * BST);
        char*       hn = (char*)(hbuf + ((t + 1) & 1) * 64 * BST);

        // acc += h @ Whh^T  (bf16 m16n8k16; A loaded once per m, B once per gate)
#pragma unroll
        for (int kc = 0; kc < 8; kc++) {
            uint2 va[4], vb[4];
#pragma unroll
            for (int m = 0; m < 4; m++) {
                va[m] = *(const uint2*)(hc + (m * 16 + gid) * (BST * 2) + kc * 32 + tig * 8);
                vb[m] = *(const uint2*)(hc + (m * 16 + 8 + gid) * (BST * 2) + kc * 32 + tig * 8);
            }
#pragma unroll
            for (int g = 0; g < 4; g++) {
                uint2 b = *(const uint2*)(wbase + (g * 128 + warp * 8 + gid) * (BST * 2)
                                          + kc * 32 + tig * 8);
#pragma unroll
                for (int m = 0; m < 4; m++)
                    mma16(acc[g][m], va[m].x, vb[m].x, va[m].y, vb[m].y, b.x, b.y);
            }
        }

        // cell update (tanh.approx) + gather-ahead + h store
#pragma unroll
        for (int m = 0; m < 4; m++) {
            float hv[4];
#pragma unroll
            for (int s = 0; s < 4; s++) {
                float iv = siga(acc[0][m][s]);
                float fv = siga(acc[1][m][s]);
                float gv = tanha(acc[2][m][s]);
                float ov = siga(acc[3][m][s]);
                float c = fv * cst[m][s] + iv * gv;
                cst[m][s] = c;
                hv[s] = ov * tanha(c);
            }
            if (t < 15) {   // prefetch next step's gate init into freed acc regs
                const float* PA = g_P + (size_t)snbr[(m * 16 + gid) * 16 + t + 1] * 512;
                const float* PB = g_P + (size_t)snbr[(m * 16 + 8 + gid) * 16 + t + 1] * 512;
#pragma unroll
                for (int g = 0; g < 4; g++) {
                    float2 va = *(const float2*)&PA[g * 128 + cb];
                    float2 vb = *(const float2*)&PB[g * 128 + cb];
                    acc[g][m][0] = va.x; acc[g][m][1] = va.y;
                    acc[g][m][2] = vb.x; acc[g][m][3] = vb.y;
                }
            }
            *(unsigned*)(hn + (m * 16 + gid) * (BST * 2) + phys * 2)     = packbf2(hv[1], hv[0]);
            *(unsigned*)(hn + (m * 16 + 8 + gid) * (BST * 2) + phys * 2) = packbf2(hv[3], hv[2]);
        }
        __syncthreads();
    }

    // final hidden in buffer 0; un-permute to g_Hn fp32
    const __nv_bfloat16* hf = hbuf;
    for (int i = tid; i < 64 * 128; i += 512) {
        int r = i >> 7, uu = i & 127;
        if (base + r < NN)
            g_Hn[(size_t)(base + r) * 128 + uu] = __bfloat162float(hf[r * BST + perm16(uu)]);
    }
}

// ---------------- out: o = x@Wself^T + hN@Wneigh^T + b  (+ ReLU / sigmoid) ----------------
template<int HOUT, int ACT>
__global__ void __launch_bounds__(512, 1) out_kernel(const float* __restrict__ xext, int sel,
                                                     float* __restrict__ oext, int osel) {
    extern __shared__ float sm[];
    float* xs = sm;
    float* h2 = xs + 64 * HSZ;
    float* ws = h2 + 64 * HSZ;
    float* wn = ws + HOUT * WFT;
    const float* x = sel ? g_H : xext;
    float* o = osel ? oext : g_H;
    int tid = threadIdx.x, lane = tid & 31, warp = tid >> 5;
    int wr = warp >> 2, cg = warp & 3, gid = lane >> 2, tig = lane & 3;
    int base = blockIdx.x * 64;
    int rowA = wr * 16 + gid, rowB = rowA + 8;
    bool vA = base + rowA < NN, vB = base + rowB < NN;

#pragma unroll
    for (int i = 0; i < 4; i++) {
        int idx = tid + i * 512;
        int r = idx >> 5, c = idx & 31;
        if (base + r < NN) {
            cpa16(xs + r * HSZ + c * 4, x    + (size_t)(base + r) * 128 + c * 4);
            cpa16(h2 + r * HSZ + c * 4, g_Hn + (size_t)(base + r) * 128 + c * 4);
        }
    }
#pragma unroll
    for (int i = 0; i < HOUT * 32 / 512; i++) {
        int idx = tid + i * 512;
        int n = idx >> 5, c = idx & 31;
        cpa16(ws + n * WFT + c * 4, g_Wself  + n * 128 + c * 4);
        cpa16(wn + n * WFT + c * 4, g_Wneigh + n * 128 + c * 4);
    }
    cpcommit();
    asm volatile("cp.async.wait_group 0;");
    __syncthreads();

    constexpr int T = HOUT / 32;
    float acc[T][4];
#pragma unroll
    for (int tt = 0; tt < T; tt++)
#pragma unroll
        for (int s = 0; s < 4; s++) acc[tt][s] = 0.f;

#pragma unroll
    for (int p = 0; p < 2; p++) {
        const float* As = p ? h2 : xs;
        const float* W  = p ? wn : ws;
#pragma unroll
        for (int kc = 0; kc < 16; kc++) {
            int kk = kc * 8;
            unsigned a0 = tf32u(As[rowA * HSZ + kk + tig]);
            unsigned a1 = tf32u(As[rowB * HSZ + kk + tig]);
            unsigned a2 = tf32u(As[rowA * HSZ + kk + tig + 4]);
            unsigned a3 = tf32u(As[rowB * HSZ + kk + tig + 4]);
#pragma unroll
            for (int tt = 0; tt < T; tt++) {
                float2 b = *(const float2*)&W[(cg * (HOUT / 4) + tt * 8 + gid) * WFT
                                              + kk + 2 * tig];
                mma8(acc[tt], a0, a1, a2, a3, __float_as_uint(b.x), __float_as_uint(b.y));
            }
        }
    }
#pragma unroll
    for (int tt = 0; tt < T; tt++)
#pragma unroll
        for (int s = 0; s < 4; s++) {
            int u = cg * (HOUT / 4) + tt * 8 + 2 * tig + (s & 1);
            float v = acc[tt][s] + g_bout[u];
            v = ACT ? sigf(v) : fmaxf(v, 0.f);
            int row = (s < 2) ? rowA : rowB;
            bool vv = (s < 2) ? vA : vB;
            if (vv) o[(size_t)(base + row) * HOUT + u] = v;
        }
}

// ---------------- launch ----------------
extern "C" void kernel_launch(void* const* d_in, const int* in_sizes, int n_in,
                              void* d_out, int out_size) {
    const float* feats = (const float*)d_in[0];
    const int*   nbr   = (const int*)d_in[1];

    const int PSM  = (64 * HSZ + 2 * 512 * WST) * 4;                 // 197632
    const int LSM  = 512 * BST * 2 + 2 * 64 * BST * 2 + 64 * 16 * 4; // 188416
    const int OSM1 = (2 * 64 * HSZ + 2 * 128 * WFT) * 4;             // 206848
    const int OSM2 = (2 * 64 * HSZ + 2 * 64 * WFT) * 4;              // 137216
    cudaFuncSetAttribute(proj_kernel,       cudaFuncAttributeMaxDynamicSharedMemorySize, PSM);
    cudaFuncSetAttribute(lstm_kernel,       cudaFuncAttributeMaxDynamicSharedMemorySize, LSM);
    cudaFuncSetAttribute(out_kernel<128,0>, cudaFuncAttributeMaxDynamicSharedMemorySize, OSM1);
    cudaFuncSetAttribute(out_kernel<64,1>,  cudaFuncAttributeMaxDynamicSharedMemorySize, OSM2);

    dim3 g(NBLK), b(512);

    // layer 1
    prep_kernel<<<256, 256>>>((const float*)d_in[2], (const float*)d_in[3],
                              (const float*)d_in[4], (const float*)d_in[5],
                              (const float*)d_in[6], (const float*)d_in[7],
                              (const float*)d_in[8], 128);
    proj_kernel<<<g, b, PSM>>>(feats, 0);
    lstm_kernel<<<g, b, LSM>>>(nbr);
    out_kernel<128, 0><<<g, b, OSM1>>>(feats, 0, nullptr, 0);

    // layer 2
    prep_kernel<<<256, 256>>>((const float*)d_in[9],  (const float*)d_in[10],
                              (const float*)d_in[11], (const float*)d_in[12],
                              (const float*)d_in[13], (const float*)d_in[14],
                              (const float*)d_in[15], 64);
    proj_kernel<<<g, b, PSM>>>(nullptr, 1);
    lstm_kernel<<<g, b, LSM>>>(nbr);
    out_kernel<64, 1><<<g, b, OSM2>>>(nullptr, 1, (float*)d_out, 1);
}